// round 5
// baseline (speedup 1.0000x reference)
#include <cuda_runtime.h>
#include <math.h>

// ---------------------------------------------------------------------------
// Problem constants
// ---------------------------------------------------------------------------
#define B_    4
#define NSEQ  4096
#define DMOD  512
#define NHEAD 8
#define DH    64
#define MLAND 256
#define LTOK  16            // NSEQ / MLAND / ... tokens per landmark = n/M = 16
#define ROWS  (B_ * NSEQ)   // 16384
#define BHB   (B_ * NHEAD)  // 32
#define SCALE_Q 0.125f      // DH^-0.5

// ---------------------------------------------------------------------------
// Scratch (static device allocations; no cudaMalloc allowed)
// ---------------------------------------------------------------------------
__device__ float g_xn[ROWS * DMOD];                 // layernorm output (reused ln1/ln2)
__device__ float g_qkv[ROWS * 3 * DMOD];            // (b,n,1536)
__device__ float g_qland[BHB * MLAND * DH];
__device__ float g_kland[BHB * MLAND * DH];
__device__ float g_attn1[BHB * NSEQ * MLAND];       // (bh, n, m)
__device__ float g_attn2[BHB * MLAND * MLAND];      // (bh, m, m)
__device__ float g_attn3[BHB * MLAND * NSEQ];       // (bh, m, n)
__device__ float g_z0[BHB * MLAND * MLAND];
__device__ float g_z1[BHB * MLAND * MLAND];
__device__ float g_xz[BHB * MLAND * MLAND];
__device__ float g_u[BHB * MLAND * MLAND];
__device__ float g_v2[BHB * MLAND * MLAND];
__device__ float g_w3v[BHB * MLAND * DH];           // attn3 @ v
__device__ float g_t[BHB * NSEQ * MLAND];           // attn1 @ attn2_inv
__device__ float g_attnout[ROWS * DMOD];            // heads reassembled (b,n,512)
__device__ float g_x2[ROWS * DMOD];                 // x + attn
__device__ float g_h1[ROWS * 4 * DMOD];             // ff hidden
__device__ int   g_norm_a;                          // max abs row-sum (bits)
__device__ int   g_norm_b;                          // max abs col-sum (bits)
__device__ float g_zscale;

// ---------------------------------------------------------------------------
// Reductions
// ---------------------------------------------------------------------------
__device__ __forceinline__ float warp_sum(float v) {
#pragma unroll
    for (int o = 16; o; o >>= 1) v += __shfl_xor_sync(0xffffffffu, v, o);
    return v;
}
__device__ __forceinline__ float warp_max(float v) {
#pragma unroll
    for (int o = 16; o; o >>= 1) v = fmaxf(v, __shfl_xor_sync(0xffffffffu, v, o));
    return v;
}
__device__ float block_sum(float v) {
    __shared__ float sh[32];
    int lane = threadIdx.x & 31, wid = threadIdx.x >> 5;
    v = warp_sum(v);
    __syncthreads();                 // protect sh reuse across calls
    if (lane == 0) sh[wid] = v;
    __syncthreads();
    int nw = blockDim.x >> 5;
    float r = (lane < nw) ? sh[lane] : 0.f;
    return warp_sum(r);
}
__device__ float block_max(float v) {
    __shared__ float sh[32];
    int lane = threadIdx.x & 31, wid = threadIdx.x >> 5;
    v = warp_max(v);
    __syncthreads();
    if (lane == 0) sh[wid] = v;
    __syncthreads();
    int nw = blockDim.x >> 5;
    float r = (lane < nw) ? sh[lane] : -3.0e38f;
    return warp_max(r);
}

__device__ __forceinline__ float gelu_f(float x) {
    return 0.5f * x * (1.f + erff(x * 0.7071067811865476f));
}

// ---------------------------------------------------------------------------
// Generic batched SGEMM: C = act(alpha * A @ B' + bias) + add
//   B' = B            (transB=0, iminus=0)       B is K x N (ldb)
//   B' = B^T          (transB=1)                 B is N x K (ldb)
//   B' = cdiag*I - B  (iminus=1, NN only)
// Batched over grid.z with (b,h) decomposed strides.
// All of M,N multiples of 64; K multiple of 16.
// ---------------------------------------------------------------------------
#define BMT 64
#define BNT 64
#define BKT 16

__global__ __launch_bounds__(256)
void gemm_kernel(const float* __restrict__ A, const float* __restrict__ B,
                 float* __restrict__ C,
                 int M, int N, int K, int lda, int ldb, int ldc,
                 int nH,
                 long long sAb, long long sAh, long long sBb, long long sBh,
                 long long sCb, long long sCh,
                 float alpha, float cdiag, int transB, int iminus, int act,
                 const float* __restrict__ bias, const float* __restrict__ addsrc) {
    __shared__ float As[BKT][BMT];
    __shared__ float Bs[BKT][BNT];
    int z = blockIdx.z;
    int zb = z / nH, zh = z - zb * nH;
    A += zb * sAb + zh * sAh;
    B += zb * sBb + zh * sBh;
    long long coff = zb * sCb + zh * sCh;
    C += coff;

    const int m0 = blockIdx.y * BMT;
    const int n0 = blockIdx.x * BNT;
    const int tid = threadIdx.x;
    const int tx = tid & 15, ty = tid >> 4;

    float acc[4][4];
#pragma unroll
    for (int i = 0; i < 4; i++)
#pragma unroll
        for (int j = 0; j < 4; j++) acc[i][j] = 0.f;

    const int aml = tid >> 2;            // 0..63
    const int akl = (tid & 3) << 2;      // 0,4,8,12

    for (int k0 = 0; k0 < K; k0 += BKT) {
        // A tile (BM x BK), stored transposed As[k][m]
        {
            float4 av = *reinterpret_cast<const float4*>(
                A + (long long)(m0 + aml) * lda + k0 + akl);
            As[akl + 0][aml] = av.x;
            As[akl + 1][aml] = av.y;
            As[akl + 2][aml] = av.z;
            As[akl + 3][aml] = av.w;
        }
        if (!transB) {
            int kl = tid >> 4;           // 0..15
            int nl = (tid & 15) << 2;    // 0..60
            float4 bv = *reinterpret_cast<const float4*>(
                B + (long long)(k0 + kl) * ldb + n0 + nl);
            if (iminus) {
                int kg = k0 + kl, ng = n0 + nl;
                bv.x = ((kg == ng + 0) ? cdiag : 0.f) - bv.x;
                bv.y = ((kg == ng + 1) ? cdiag : 0.f) - bv.y;
                bv.z = ((kg == ng + 2) ? cdiag : 0.f) - bv.z;
                bv.w = ((kg == ng + 3) ? cdiag : 0.f) - bv.w;
            }
            Bs[kl][nl + 0] = bv.x;
            Bs[kl][nl + 1] = bv.y;
            Bs[kl][nl + 2] = bv.z;
            Bs[kl][nl + 3] = bv.w;
        } else {
            int nl = tid >> 2;           // 0..63
            int kl = (tid & 3) << 2;     // 0,4,8,12
            float4 bv = *reinterpret_cast<const float4*>(
                B + (long long)(n0 + nl) * ldb + k0 + kl);
            Bs[kl + 0][nl] = bv.x;
            Bs[kl + 1][nl] = bv.y;
            Bs[kl + 2][nl] = bv.z;
            Bs[kl + 3][nl] = bv.w;
        }
        __syncthreads();
#pragma unroll
        for (int kk = 0; kk < BKT; kk++) {
            float4 a = *reinterpret_cast<const float4*>(&As[kk][ty << 2]);
            float4 b = *reinterpret_cast<const float4*>(&Bs[kk][tx << 2]);
            acc[0][0] += a.x * b.x; acc[0][1] += a.x * b.y;
            acc[0][2] += a.x * b.z; acc[0][3] += a.x * b.w;
            acc[1][0] += a.y * b.x; acc[1][1] += a.y * b.y;
            acc[1][2] += a.y * b.z; acc[1][3] += a.y * b.w;
            acc[2][0] += a.z * b.x; acc[2][1] += a.z * b.y;
            acc[2][2] += a.z * b.z; acc[2][3] += a.z * b.w;
            acc[3][0] += a.w * b.x; acc[3][1] += a.w * b.y;
            acc[3][2] += a.w * b.z; acc[3][3] += a.w * b.w;
        }
        __syncthreads();
    }

#pragma unroll
    for (int i = 0; i < 4; i++) {
        int m = m0 + (ty << 2) + i;
#pragma unroll
        for (int j = 0; j < 4; j++) {
            int nn = n0 + (tx << 2) + j;
            float v = alpha * acc[i][j];
            if (bias) v += bias[nn];
            if (act) v = gelu_f(v);
            if (addsrc) v += addsrc[coff + (long long)m * ldc + nn];
            C[(long long)m * ldc + nn] = v;
        }
    }
}

// ---------------------------------------------------------------------------
// LayerNorm: one block of 128 threads per row (D=512)
// ---------------------------------------------------------------------------
__global__ __launch_bounds__(128)
void layernorm_kernel(const float* __restrict__ x, const float* __restrict__ g,
                      const float* __restrict__ b, float* __restrict__ out) {
    long long row = blockIdx.x;
    const float* xr = x + row * DMOD;
    float v[4];
    float s = 0.f;
#pragma unroll
    for (int i = 0; i < 4; i++) { v[i] = xr[i * 128 + threadIdx.x]; s += v[i]; }
    s = block_sum(s);
    float mu = s * (1.f / DMOD);
    float s2 = 0.f;
#pragma unroll
    for (int i = 0; i < 4; i++) { float d = v[i] - mu; s2 += d * d; }
    s2 = block_sum(s2);
    float rstd = rsqrtf(s2 * (1.f / DMOD) + 1e-5f);
#pragma unroll
    for (int i = 0; i < 4; i++) {
        int c = i * 128 + threadIdx.x;
        out[row * DMOD + c] = (v[i] - mu) * rstd * g[c] + b[c];
    }
}

// ---------------------------------------------------------------------------
// Landmark means: q_land/k_land[bh][m][d] = mean over 16 tokens (unscaled)
// ---------------------------------------------------------------------------
__global__ __launch_bounds__(64)
void landmark_kernel(const float* __restrict__ qkv, float* __restrict__ qland,
                     float* __restrict__ kland) {
    int idx = blockIdx.x;            // bh*256 + m
    int m = idx & 255;
    int bh = idx >> 8;
    int b = bh >> 3, h = bh & 7;
    int d = threadIdx.x;
    const float* base =
        qkv + ((long long)(b * NSEQ + m * LTOK)) * 1536 + h * 64 + d;
    float sq = 0.f, sk = 0.f;
#pragma unroll
    for (int i = 0; i < LTOK; i++) {
        sq += base[(long long)i * 1536];
        sk += base[(long long)i * 1536 + 512];
    }
    long long o = ((long long)bh * 256 + m) * 64 + d;
    qland[o] = sq * (1.f / 16.f);
    kland[o] = sk * (1.f / 16.f);
}

// ---------------------------------------------------------------------------
// Row softmax, 256 threads per row, PER elements per thread
// ---------------------------------------------------------------------------
template <int PER>
__global__ __launch_bounds__(256)
void softmax_kernel(float* __restrict__ x) {
    float* xr = x + (long long)blockIdx.x * (PER * 256);
    float v[PER];
    float mx = -3.0e38f;
#pragma unroll
    for (int i = 0; i < PER; i++) {
        v[i] = xr[i * 256 + threadIdx.x];
        mx = fmaxf(mx, v[i]);
    }
    mx = block_max(mx);
    float s = 0.f;
#pragma unroll
    for (int i = 0; i < PER; i++) { v[i] = __expf(v[i] - mx); s += v[i]; }
    s = block_sum(s);
    float inv = 1.f / s;
#pragma unroll
    for (int i = 0; i < PER; i++) xr[i * 256 + threadIdx.x] = v[i] * inv;
}

// ---------------------------------------------------------------------------
// Pinv helpers
// ---------------------------------------------------------------------------
__global__ void pinv_reset() { g_norm_a = 0; g_norm_b = 0; }

__global__ __launch_bounds__(256)
void pinv_absrowmax(const float* __restrict__ a2) {
    long long r = blockIdx.x;        // bh*256 + i
    float s = block_sum(fabsf(a2[r * 256 + threadIdx.x]));
    if (threadIdx.x == 0) atomicMax(&g_norm_a, __float_as_int(s));
}
__global__ __launch_bounds__(256)
void pinv_abscolmax(const float* __restrict__ a2) {
    int bh = blockIdx.x >> 8, j = blockIdx.x & 255;
    float s = block_sum(fabsf(a2[((long long)bh << 16) + threadIdx.x * 256 + j]));
    if (threadIdx.x == 0) atomicMax(&g_norm_b, __float_as_int(s));
}
__global__ void pinv_finalize() {
    g_zscale = 1.f / (__int_as_float(g_norm_a) * __int_as_float(g_norm_b));
}
__global__ __launch_bounds__(256)
void pinv_initz(const float* __restrict__ a2, float* __restrict__ z) {
    int idx = blockIdx.x * 256 + threadIdx.x;   // 32*65536 total
    int j = idx & 255;
    int i = (idx >> 8) & 255;
    int bh = idx >> 16;
    z[idx] = a2[((long long)bh << 16) + (j << 8) + i] * g_zscale;
}

// ---------------------------------------------------------------------------
// Depthwise conv residual (kernel 33, pad 16) added into attn_out
// ---------------------------------------------------------------------------
__global__ __launch_bounds__(256)
void convres_kernel(const float* __restrict__ qkv, const float* __restrict__ w,
                    float* __restrict__ out) {
    int idx = blockIdx.x * 256 + threadIdx.x;   // 4*4096*8*64
    int d = idx & 63;
    int h = (idx >> 6) & 7;
    int i = (idx >> 9) & 4095;
    int b = idx >> 21;
    const float* wr = w + h * 33;
    const float* vbase =
        qkv + (long long)b * NSEQ * 1536 + 1024 + h * 64 + d;
    float acc = 0.f;
#pragma unroll
    for (int t = 0; t < 33; t++) {
        int ii = i + t - 16;
        if (ii >= 0 && ii < NSEQ) acc += wr[t] * vbase[(long long)ii * 1536];
    }
    out[((long long)(b * NSEQ + i) << 9) + (h << 6) + d] += acc;
}

// ---------------------------------------------------------------------------
// Host orchestration
// ---------------------------------------------------------------------------
static void gemm(const float* A, const float* B, float* C, int M, int N, int K,
                 int lda, int ldb, int ldc, int Z, int nH,
                 long long sAb, long long sAh, long long sBb, long long sBh,
                 long long sCb, long long sCh,
                 float alpha, float cdiag, int transB, int iminus, int act,
                 const float* bias, const float* add) {
    dim3 grid(N / BNT, M / BMT, Z);
    gemm_kernel<<<grid, 256>>>(A, B, C, M, N, K, lda, ldb, ldc, nH,
                               sAb, sAh, sBb, sBh, sCb, sCh,
                               alpha, cdiag, transB, iminus, act, bias, add);
}

extern "C" void kernel_launch(void* const* d_in, const int* in_sizes, int n_in,
                              void* d_out, int out_size) {
    const float* x      = (const float*)d_in[0];
    const float* ln1_g  = (const float*)d_in[1];
    const float* ln1_b  = (const float*)d_in[2];
    const float* w_qkv  = (const float*)d_in[3];
    const float* conv_w = (const float*)d_in[4];
    const float* w_out  = (const float*)d_in[5];
    const float* b_out  = (const float*)d_in[6];
    const float* ln2_g  = (const float*)d_in[7];
    const float* ln2_b  = (const float*)d_in[8];
    const float* w_ff1  = (const float*)d_in[9];
    const float* b_ff1  = (const float*)d_in[10];
    const float* w_ff2  = (const float*)d_in[11];
    const float* b_ff2  = (const float*)d_in[12];
    float* out = (float*)d_out;

    void* p;
    float *xn, *qkvb, *qland, *kland, *a1, *a2, *a3, *z0, *z1, *xz, *u, *v2,
        *w3v, *tb, *aout, *x2, *h1;
    cudaGetSymbolAddress(&p, g_xn);      xn    = (float*)p;
    cudaGetSymbolAddress(&p, g_qkv);     qkvb  = (float*)p;
    cudaGetSymbolAddress(&p, g_qland);   qland = (float*)p;
    cudaGetSymbolAddress(&p, g_kland);   kland = (float*)p;
    cudaGetSymbolAddress(&p, g_attn1);   a1    = (float*)p;
    cudaGetSymbolAddress(&p, g_attn2);   a2    = (float*)p;
    cudaGetSymbolAddress(&p, g_attn3);   a3    = (float*)p;
    cudaGetSymbolAddress(&p, g_z0);      z0    = (float*)p;
    cudaGetSymbolAddress(&p, g_z1);      z1    = (float*)p;
    cudaGetSymbolAddress(&p, g_xz);      xz    = (float*)p;
    cudaGetSymbolAddress(&p, g_u);       u     = (float*)p;
    cudaGetSymbolAddress(&p, g_v2);      v2    = (float*)p;
    cudaGetSymbolAddress(&p, g_w3v);     w3v   = (float*)p;
    cudaGetSymbolAddress(&p, g_t);       tb    = (float*)p;
    cudaGetSymbolAddress(&p, g_attnout); aout  = (float*)p;
    cudaGetSymbolAddress(&p, g_x2);      x2    = (float*)p;
    cudaGetSymbolAddress(&p, g_h1);      h1    = (float*)p;

    const long long sQb = (long long)NSEQ * 1536;   // qkv per-b stride
    const long long sLh = (long long)MLAND * DH;    // landmark per-h
    const long long sLb = 8 * sLh;
    const long long sA1h = (long long)NSEQ * MLAND; // attn1 per-h
    const long long sA1b = 8 * sA1h;
    const long long sA2h = (long long)MLAND * MLAND;
    const long long sA2b = 8 * sA2h;
    const long long sA3h = (long long)MLAND * NSEQ;
    const long long sA3b = 8 * sA3h;

    // 1. LN1
    layernorm_kernel<<<ROWS, 128>>>(x, ln1_g, ln1_b, xn);
    // 2. QKV projection
    gemm(xn, w_qkv, qkvb, ROWS, 1536, 512, 512, 1536, 1536, 1, 1,
         0, 0, 0, 0, 0, 0, 1.f, 0.f, 0, 0, 0, nullptr, nullptr);
    // 3. Landmark means
    landmark_kernel<<<BHB * MLAND, 64>>>(qkvb, qland, kland);
    // 4. sim1 = scale * q @ k_land^T      (4096 x 256, K=64)
    gemm(qkvb, kland, a1, NSEQ, MLAND, DH, 1536, 64, MLAND, BHB, 8,
         sQb, 64, sLb, sLh, sA1b, sA1h, SCALE_Q, 0.f, 1, 0, 0, nullptr, nullptr);
    // 5. sim2 = scale * q_land @ k_land^T (256 x 256, K=64)
    gemm(qland, kland, a2, MLAND, MLAND, DH, 64, 64, MLAND, BHB, 8,
         sLb, sLh, sLb, sLh, sA2b, sA2h, SCALE_Q, 0.f, 1, 0, 0, nullptr, nullptr);
    // 6. sim3 = scale * q_land @ k^T      (256 x 4096, K=64)
    gemm(qland, qkvb + 512, a3, MLAND, NSEQ, DH, 64, 1536, NSEQ, BHB, 8,
         sLb, sLh, sQb, 64, sA3b, sA3h, SCALE_Q, 0.f, 1, 0, 0, nullptr, nullptr);
    // 7. softmaxes
    softmax_kernel<1><<<BHB * NSEQ, 256>>>(a1);
    softmax_kernel<1><<<BHB * MLAND, 256>>>(a2);
    softmax_kernel<16><<<BHB * MLAND, 256>>>(a3);
    // 8. pinv init
    pinv_reset<<<1, 1>>>();
    pinv_absrowmax<<<BHB * MLAND, 256>>>(a2);
    pinv_abscolmax<<<BHB * MLAND, 256>>>(a2);
    pinv_finalize<<<1, 1>>>();
    pinv_initz<<<(BHB * MLAND * MLAND) / 256, 256>>>(a2, z0);
    // 9. 6 Newton-Schulz style iterations, I-minus folded into GEMM B-load
    float* zA = z0;
    float* zB = z1;
    for (int it = 0; it < 6; it++) {
        gemm(a2, zA, xz, MLAND, MLAND, MLAND, 256, 256, 256, BHB, 8,
             sA2b, sA2h, sA2b, sA2h, sA2b, sA2h, 1.f, 0.f, 0, 0, 0, nullptr, nullptr);
        gemm(xz, xz, u, MLAND, MLAND, MLAND, 256, 256, 256, BHB, 8,
             sA2b, sA2h, sA2b, sA2h, sA2b, sA2h, 1.f, 7.f, 0, 1, 0, nullptr, nullptr);
        gemm(xz, u, v2, MLAND, MLAND, MLAND, 256, 256, 256, BHB, 8,
             sA2b, sA2h, sA2b, sA2h, sA2b, sA2h, 1.f, 15.f, 0, 1, 0, nullptr, nullptr);
        gemm(zA, v2, zB, MLAND, MLAND, MLAND, 256, 256, 256, BHB, 8,
             sA2b, sA2h, sA2b, sA2h, sA2b, sA2h, 0.25f, 13.f, 0, 1, 0, nullptr, nullptr);
        float* tmp = zA; zA = zB; zB = tmp;
    }
    // 10. w3v = attn3 @ v   (256 x 64, K=4096)
    gemm(a3, qkvb + 1024, w3v, MLAND, DH, NSEQ, NSEQ, 1536, DH, BHB, 8,
         sA3b, sA3h, sQb, 64, sLb, sLh, 1.f, 0.f, 0, 0, 0, nullptr, nullptr);
    // 11. t = attn1 @ attn2_inv   (4096 x 256, K=256)
    gemm(a1, zA, tb, NSEQ, MLAND, MLAND, 256, 256, 256, BHB, 8,
         sA1b, sA1h, sA2b, sA2h, sA1b, sA1h, 1.f, 0.f, 0, 0, 0, nullptr, nullptr);
    // 12. out_heads = t @ w3v  -> into (b,n,512) at column h*64
    gemm(tb, w3v, aout, NSEQ, DH, MLAND, 256, 64, 512, BHB, 8,
         sA1b, sA1h, sLb, sLh, (long long)NSEQ * 512, 64,
         1.f, 0.f, 0, 0, 0, nullptr, nullptr);
    // 13. depthwise conv residual, += into aout
    convres_kernel<<<(B_ * NSEQ * NHEAD * DH) / 256, 256>>>(qkvb, conv_w, aout);
    // 14. out projection + bias + residual(x)  -> x2
    gemm(aout, w_out, x2, ROWS, 512, 512, 512, 512, 512, 1, 1,
         0, 0, 0, 0, 0, 0, 1.f, 0.f, 0, 0, 0, b_out, x);
    // 15. LN2
    layernorm_kernel<<<ROWS, 128>>>(x2, ln2_g, ln2_b, xn);
    // 16. FF1 + bias + exact GELU
    gemm(xn, w_ff1, h1, ROWS, 2048, 512, 512, 2048, 2048, 1, 1,
         0, 0, 0, 0, 0, 0, 1.f, 0.f, 0, 0, 1, b_ff1, nullptr);
    // 17. FF2 + bias + residual(x2) -> out
    gemm(h1, w_ff2, out, ROWS, 512, 2048, 2048, 512, 512, 1, 1,
         0, 0, 0, 0, 0, 0, 1.f, 0.f, 0, 0, 0, b_ff2, x2);
}

// round 8
// speedup vs baseline: 2.6395x; 2.6395x over previous
#include <cuda_runtime.h>
#include <math.h>
#include <stdint.h>

// ---------------------------------------------------------------------------
// Problem constants
// ---------------------------------------------------------------------------
#define B_    4
#define NSEQ  4096
#define DMOD  512
#define NHEAD 8
#define DH    64
#define MLAND 256
#define LTOK  16
#define ROWS  (B_ * NSEQ)   // 16384
#define BHB   (B_ * NHEAD)  // 32
#define SCALE_Q 0.125f

// ---------------------------------------------------------------------------
// Scratch (static device allocations; no cudaMalloc allowed)
// ---------------------------------------------------------------------------
__device__ float g_xn[ROWS * DMOD];
__device__ float g_qkv[ROWS * 3 * DMOD];
__device__ float g_qland[BHB * MLAND * DH];
__device__ float g_kland[BHB * MLAND * DH];
__device__ float g_attn1[BHB * NSEQ * MLAND];
__device__ float g_attn2[BHB * MLAND * MLAND];
__device__ float g_attn3[BHB * MLAND * NSEQ];
__device__ float g_z0[BHB * MLAND * MLAND];
__device__ float g_z1[BHB * MLAND * MLAND];
__device__ float g_xz[BHB * MLAND * MLAND];
__device__ float g_u[BHB * MLAND * MLAND];
__device__ float g_v2[BHB * MLAND * MLAND];
__device__ float g_w3v[BHB * MLAND * DH];
__device__ float g_t[BHB * NSEQ * MLAND];
__device__ float g_attnout[ROWS * DMOD];
__device__ float g_x2[ROWS * DMOD];
__device__ float g_h1[ROWS * 4 * DMOD];
__device__ int   g_norm_a;
__device__ int   g_norm_b;
__device__ float g_zscale;

// ---------------------------------------------------------------------------
// Reductions
// ---------------------------------------------------------------------------
__device__ __forceinline__ float warp_sum(float v) {
#pragma unroll
    for (int o = 16; o; o >>= 1) v += __shfl_xor_sync(0xffffffffu, v, o);
    return v;
}
__device__ __forceinline__ float warp_max(float v) {
#pragma unroll
    for (int o = 16; o; o >>= 1) v = fmaxf(v, __shfl_xor_sync(0xffffffffu, v, o));
    return v;
}
__device__ float block_sum(float v) {
    __shared__ float sh[32];
    int lane = threadIdx.x & 31, wid = threadIdx.x >> 5;
    v = warp_sum(v);
    __syncthreads();
    if (lane == 0) sh[wid] = v;
    __syncthreads();
    int nw = blockDim.x >> 5;
    float r = (lane < nw) ? sh[lane] : 0.f;
    return warp_sum(r);
}
__device__ float block_max(float v) {
    __shared__ float sh[32];
    int lane = threadIdx.x & 31, wid = threadIdx.x >> 5;
    v = warp_max(v);
    __syncthreads();
    if (lane == 0) sh[wid] = v;
    __syncthreads();
    int nw = blockDim.x >> 5;
    float r = (lane < nw) ? sh[lane] : -3.0e38f;
    return warp_max(r);
}

__device__ __forceinline__ float gelu_f(float x) {
    return 0.5f * x * (1.f + erff(x * 0.7071067811865476f));
}

__device__ __forceinline__ uint32_t f2tf(float x) {
    uint32_t r;
    asm("cvt.rna.tf32.f32 %0, %1;" : "=r"(r) : "f"(x));
    return r;
}

__device__ __forceinline__ void mma_tf32(float* c, const uint32_t* a,
                                         const uint32_t* b) {
    asm volatile(
        "mma.sync.aligned.m16n8k8.row.col.f32.tf32.tf32.f32 "
        "{%0,%1,%2,%3}, {%4,%5,%6,%7}, {%8,%9}, {%0,%1,%2,%3};\n"
        : "+f"(c[0]), "+f"(c[1]), "+f"(c[2]), "+f"(c[3])
        : "r"(a[0]), "r"(a[1]), "r"(a[2]), "r"(a[3]), "r"(b[0]), "r"(b[1]));
}

// ---------------------------------------------------------------------------
// TF32 tensor-core batched GEMM: C = act(alpha * A @ B' + bias) + add
//   TRANSB=0: B' = B (K x N), optional iminus: B' = cdiag*I - B
//   TRANSB=1: B' = B^T (B is N x K)
// BN=64, BK=32 fixed. 256 threads, WARPS_M x WARPS_N warp grid.
// M % BM == 0, N % 64 == 0, K % 32 == 0.
// ---------------------------------------------------------------------------
#define GBK 32
#define GBN 64

template <int BM, int WARPS_M, int WARPS_N, int TRANSB>
__global__ __launch_bounds__(256)
void gemm_tc(const float* __restrict__ A, const float* __restrict__ B,
             float* __restrict__ C,
             int M, int N, int K, int lda, int ldb, int ldc, int nH,
             long long sAb, long long sAh, long long sBb, long long sBh,
             long long sCb, long long sCh,
             float alpha, float cdiag, int iminus, int act,
             const float* __restrict__ bias, const float* __restrict__ addsrc) {
    constexpr int AP  = GBK + 4;            // 36 : As pitch (floats)
    constexpr int BPN = GBN + 8;            // 72 : Bs pitch for NN [k][n]
    constexpr int BPT = GBK + 4;            // 36 : Bs pitch for TT [n][k]
    constexpr int ASZ = BM * AP;
    constexpr int BSZ = 2304;               // = 32*72 = 64*36
    constexpr int WM  = BM / WARPS_M;       // 32
    constexpr int WN  = GBN / WARPS_N;      // 32 or 16
    constexpr int MF  = WM / 16;            // 2
    constexpr int NF  = WN / 8;             // 4 or 2
    constexpr int AV  = (BM * GBK) / (256 * 4);  // float4 of A per thread

    extern __shared__ float smbuf[];
    float* As = smbuf;              // [2][ASZ]
    float* Bs = smbuf + 2 * ASZ;    // [2][BSZ]

    const int z = blockIdx.z;
    const int zb = z / nH, zh = z - zb * nH;
    A += zb * sAb + zh * sAh;
    B += zb * sBb + zh * sBh;
    const long long coff = zb * sCb + zh * sCh;
    C += coff;

    const int m0 = blockIdx.y * BM;
    const int n0 = blockIdx.x * GBN;
    const int tid = threadIdx.x;
    const int lane = tid & 31;
    const int g = lane >> 2, t4 = lane & 3;
    const int wid = tid >> 5;
    const int wm = wid / WARPS_N;
    const int wn = wid % WARPS_N;

    float acc[MF][NF][4];
#pragma unroll
    for (int mi = 0; mi < MF; mi++)
#pragma unroll
        for (int ni = 0; ni < NF; ni++)
#pragma unroll
            for (int q = 0; q < 4; q++) acc[mi][ni][q] = 0.f;

    float4 ra[AV];
    float4 rb[2];

    const int KT = K / GBK;

    // ---- global load of tile kt into registers ----
    auto ldg_tile = [&](int kt) {
        const long long kb = (long long)kt * GBK;
#pragma unroll
        for (int i = 0; i < AV; i++) {
            int f = tid + 256 * i;
            int r = f >> 3;                 // 8 float4 per 32-wide row
            int kq = (f & 7) << 2;
            ra[i] = *reinterpret_cast<const float4*>(
                A + (long long)(m0 + r) * lda + kb + kq);
        }
        if (TRANSB) {
#pragma unroll
            for (int i = 0; i < 2; i++) {
                int f = tid + 256 * i;
                int nn = f >> 3;
                int kq = (f & 7) << 2;
                rb[i] = *reinterpret_cast<const float4*>(
                    B + (long long)(n0 + nn) * ldb + kb + kq);
            }
        } else {
#pragma unroll
            for (int i = 0; i < 2; i++) {
                int f = tid + 256 * i;
                int k = f >> 4;             // 16 float4 per 64-wide row
                int nq = (f & 15) << 2;
                rb[i] = *reinterpret_cast<const float4*>(
                    B + (long long)(kb + k) * ldb + n0 + nq);
            }
        }
    };

    // ---- cvt to tf32 + store into smem stage ----
    auto sts_tile = [&](int kt, int buf) {
        float* dA = As + buf * ASZ;
#pragma unroll
        for (int i = 0; i < AV; i++) {
            int f = tid + 256 * i;
            int r = f >> 3;
            int kq = (f & 7) << 2;
            uint4 u;
            u.x = f2tf(ra[i].x); u.y = f2tf(ra[i].y);
            u.z = f2tf(ra[i].z); u.w = f2tf(ra[i].w);
            *reinterpret_cast<uint4*>(dA + r * AP + kq) = u;
        }
        float* dB = Bs + buf * BSZ;
        if (TRANSB) {
#pragma unroll
            for (int i = 0; i < 2; i++) {
                int f = tid + 256 * i;
                int nn = f >> 3;
                int kq = (f & 7) << 2;
                uint4 u;
                u.x = f2tf(rb[i].x); u.y = f2tf(rb[i].y);
                u.z = f2tf(rb[i].z); u.w = f2tf(rb[i].w);
                *reinterpret_cast<uint4*>(dB + nn * BPT + kq) = u;
            }
        } else {
#pragma unroll
            for (int i = 0; i < 2; i++) {
                int f = tid + 256 * i;
                int k = f >> 4;
                int nq = (f & 15) << 2;
                float4 v = rb[i];
                if (iminus) {
                    int kg = kt * GBK + k, ng = n0 + nq;
                    v.x = ((kg == ng + 0) ? cdiag : 0.f) - v.x;
                    v.y = ((kg == ng + 1) ? cdiag : 0.f) - v.y;
                    v.z = ((kg == ng + 2) ? cdiag : 0.f) - v.z;
                    v.w = ((kg == ng + 3) ? cdiag : 0.f) - v.w;
                }
                uint4 u;
                u.x = f2tf(v.x); u.y = f2tf(v.y);
                u.z = f2tf(v.z); u.w = f2tf(v.w);
                *reinterpret_cast<uint4*>(dB + k * BPN + nq) = u;
            }
        }
    };

    ldg_tile(0);
    sts_tile(0, 0);
    __syncthreads();

    for (int kt = 0; kt < KT; kt++) {
        const int buf = kt & 1;
        if (kt + 1 < KT) ldg_tile(kt + 1);

        const uint32_t* pA =
            reinterpret_cast<const uint32_t*>(As + buf * ASZ) + (wm * WM) * AP;
        const uint32_t* pB = reinterpret_cast<const uint32_t*>(Bs + buf * BSZ);
#pragma unroll
        for (int ks = 0; ks < 4; ks++) {
            const int kk = ks * 8 + t4;
            uint32_t afr[MF][4];
            uint32_t bfr[NF][2];
#pragma unroll
            for (int mi = 0; mi < MF; mi++) {
                int r = mi * 16 + g;
                afr[mi][0] = pA[r * AP + kk];
                afr[mi][1] = pA[(r + 8) * AP + kk];
                afr[mi][2] = pA[r * AP + kk + 4];
                afr[mi][3] = pA[(r + 8) * AP + kk + 4];
            }
#pragma unroll
            for (int ni = 0; ni < NF; ni++) {
                int c = wn * WN + ni * 8 + g;
                if (TRANSB) {
                    bfr[ni][0] = pB[c * BPT + kk];
                    bfr[ni][1] = pB[c * BPT + kk + 4];
                } else {
                    bfr[ni][0] = pB[kk * BPN + c];
                    bfr[ni][1] = pB[(kk + 4) * BPN + c];
                }
            }
#pragma unroll
            for (int mi = 0; mi < MF; mi++)
#pragma unroll
                for (int ni = 0; ni < NF; ni++)
                    mma_tf32(acc[mi][ni], afr[mi], bfr[ni]);
        }

        if (kt + 1 < KT) {
            sts_tile(kt + 1, (kt + 1) & 1);
            __syncthreads();
        }
    }

    // ---- epilogue ----
#pragma unroll
    for (int mi = 0; mi < MF; mi++) {
#pragma unroll
        for (int ni = 0; ni < NF; ni++) {
            const int c = n0 + wn * WN + ni * 8 + t4 * 2;
            float bx = 0.f, by = 0.f;
            if (bias) { bx = bias[c]; by = bias[c + 1]; }
#pragma unroll
            for (int h2 = 0; h2 < 2; h2++) {
                const int m = m0 + wm * WM + mi * 16 + g + h2 * 8;
                float v0 = alpha * acc[mi][ni][h2 * 2 + 0] + bx;
                float v1 = alpha * acc[mi][ni][h2 * 2 + 1] + by;
                if (act) { v0 = gelu_f(v0); v1 = gelu_f(v1); }
                if (addsrc) {
                    float2 av = *reinterpret_cast<const float2*>(
                        addsrc + coff + (long long)m * ldc + c);
                    v0 += av.x; v1 += av.y;
                }
                float2 o; o.x = v0; o.y = v1;
                *reinterpret_cast<float2*>(C + (long long)m * ldc + c) = o;
            }
        }
    }
}

// ---------------------------------------------------------------------------
// LayerNorm
// ---------------------------------------------------------------------------
__global__ __launch_bounds__(128)
void layernorm_kernel(const float* __restrict__ x, const float* __restrict__ g,
                      const float* __restrict__ b, float* __restrict__ out) {
    long long row = blockIdx.x;
    const float* xr = x + row * DMOD;
    float v[4];
    float s = 0.f;
#pragma unroll
    for (int i = 0; i < 4; i++) { v[i] = xr[i * 128 + threadIdx.x]; s += v[i]; }
    s = block_sum(s);
    float mu = s * (1.f / DMOD);
    float s2 = 0.f;
#pragma unroll
    for (int i = 0; i < 4; i++) { float d = v[i] - mu; s2 += d * d; }
    s2 = block_sum(s2);
    float rstd = rsqrtf(s2 * (1.f / DMOD) + 1e-5f);
#pragma unroll
    for (int i = 0; i < 4; i++) {
        int c = i * 128 + threadIdx.x;
        out[row * DMOD + c] = (v[i] - mu) * rstd * g[c] + b[c];
    }
}

// ---------------------------------------------------------------------------
// Landmark means
// ---------------------------------------------------------------------------
__global__ __launch_bounds__(64)
void landmark_kernel(const float* __restrict__ qkv, float* __restrict__ qland,
                     float* __restrict__ kland) {
    int idx = blockIdx.x;
    int m = idx & 255;
    int bh = idx >> 8;
    int b = bh >> 3, h = bh & 7;
    int d = threadIdx.x;
    const float* base =
        qkv + ((long long)(b * NSEQ + m * LTOK)) * 1536 + h * 64 + d;
    float sq = 0.f, sk = 0.f;
#pragma unroll
    for (int i = 0; i < LTOK; i++) {
        sq += base[(long long)i * 1536];
        sk += base[(long long)i * 1536 + 512];
    }
    long long o = ((long long)bh * 256 + m) * 64 + d;
    qland[o] = sq * (1.f / 16.f);
    kland[o] = sk * (1.f / 16.f);
}

// ---------------------------------------------------------------------------
// Row softmax
// ---------------------------------------------------------------------------
template <int PER>
__global__ __launch_bounds__(256)
void softmax_kernel(float* __restrict__ x) {
    float* xr = x + (long long)blockIdx.x * (PER * 256);
    float v[PER];
    float mx = -3.0e38f;
#pragma unroll
    for (int i = 0; i < PER; i++) {
        v[i] = xr[i * 256 + threadIdx.x];
        mx = fmaxf(mx, v[i]);
    }
    mx = block_max(mx);
    float s = 0.f;
#pragma unroll
    for (int i = 0; i < PER; i++) { v[i] = __expf(v[i] - mx); s += v[i]; }
    s = block_sum(s);
    float inv = 1.f / s;
#pragma unroll
    for (int i = 0; i < PER; i++) xr[i * 256 + threadIdx.x] = v[i] * inv;
}

// ---------------------------------------------------------------------------
// Pinv helpers
// ---------------------------------------------------------------------------
__global__ void pinv_reset() { g_norm_a = 0; g_norm_b = 0; }

__global__ __launch_bounds__(256)
void pinv_absrowmax(const float* __restrict__ a2) {
    long long r = blockIdx.x;
    float s = block_sum(fabsf(a2[r * 256 + threadIdx.x]));
    if (threadIdx.x == 0) atomicMax(&g_norm_a, __float_as_int(s));
}
__global__ __launch_bounds__(256)
void pinv_abscolmax(const float* __restrict__ a2) {
    int bh = blockIdx.x >> 8, j = blockIdx.x & 255;
    float s = block_sum(fabsf(a2[((long long)bh << 16) + threadIdx.x * 256 + j]));
    if (threadIdx.x == 0) atomicMax(&g_norm_b, __float_as_int(s));
}
__global__ void pinv_finalize() {
    g_zscale = 1.f / (__int_as_float(g_norm_a) * __int_as_float(g_norm_b));
}
__global__ __launch_bounds__(256)
void pinv_initz(const float* __restrict__ a2, float* __restrict__ z) {
    int idx = blockIdx.x * 256 + threadIdx.x;
    int j = idx & 255;
    int i = (idx >> 8) & 255;
    int bh = idx >> 16;
    z[idx] = a2[((long long)bh << 16) + (j << 8) + i] * g_zscale;
}

// ---------------------------------------------------------------------------
// Depthwise conv residual (kernel 33, pad 16)
// ---------------------------------------------------------------------------
__global__ __launch_bounds__(256)
void convres_kernel(const float* __restrict__ qkv, const float* __restrict__ w,
                    float* __restrict__ out) {
    int idx = blockIdx.x * 256 + threadIdx.x;
    int d = idx & 63;
    int h = (idx >> 6) & 7;
    int i = (idx >> 9) & 4095;
    int b = idx >> 21;
    const float* wr = w + h * 33;
    const float* vbase =
        qkv + (long long)b * NSEQ * 1536 + 1024 + h * 64 + d;
    float acc = 0.f;
#pragma unroll
    for (int t = 0; t < 33; t++) {
        int ii = i + t - 16;
        if (ii >= 0 && ii < NSEQ) acc += wr[t] * vbase[(long long)ii * 1536];
    }
    out[((long long)(b * NSEQ + i) << 9) + (h << 6) + d] += acc;
}

// ---------------------------------------------------------------------------
// Host orchestration
// ---------------------------------------------------------------------------
static void gemm(const float* A, const float* B, float* C, int M, int N, int K,
                 int lda, int ldb, int ldc, int Z, int nH,
                 long long sAb, long long sAh, long long sBb, long long sBh,
                 long long sCb, long long sCh,
                 float alpha, float cdiag, int transB, int iminus, int act,
                 const float* bias, const float* add) {
    const bool bm64 = ((long long)(M / 128) * (N / 64) * Z) < 148 || (M % 128 != 0);
    if (!bm64) {
        const int smem = (2 * 128 * 36 + 2 * 2304) * 4;  // 55296
        dim3 grid(N / GBN, M / 128, Z);
        if (transB) {
            cudaFuncSetAttribute(gemm_tc<128, 4, 2, 1>,
                                 cudaFuncAttributeMaxDynamicSharedMemorySize, smem);
            gemm_tc<128, 4, 2, 1><<<grid, 256, smem>>>(
                A, B, C, M, N, K, lda, ldb, ldc, nH, sAb, sAh, sBb, sBh, sCb,
                sCh, alpha, cdiag, iminus, act, bias, add);
        } else {
            cudaFuncSetAttribute(gemm_tc<128, 4, 2, 0>,
                                 cudaFuncAttributeMaxDynamicSharedMemorySize, smem);
            gemm_tc<128, 4, 2, 0><<<grid, 256, smem>>>(
                A, B, C, M, N, K, lda, ldb, ldc, nH, sAb, sAh, sBb, sBh, sCb,
                sCh, alpha, cdiag, iminus, act, bias, add);
        }
    } else {
        const int smem = (2 * 64 * 36 + 2 * 2304) * 4;   // 36864
        dim3 grid(N / GBN, M / 64, Z);
        if (transB) {
            cudaFuncSetAttribute(gemm_tc<64, 2, 4, 1>,
                                 cudaFuncAttributeMaxDynamicSharedMemorySize, smem);
            gemm_tc<64, 2, 4, 1><<<grid, 256, smem>>>(
                A, B, C, M, N, K, lda, ldb, ldc, nH, sAb, sAh, sBb, sBh, sCb,
                sCh, alpha, cdiag, iminus, act, bias, add);
        } else {
            cudaFuncSetAttribute(gemm_tc<64, 2, 4, 0>,
                                 cudaFuncAttributeMaxDynamicSharedMemorySize, smem);
            gemm_tc<64, 2, 4, 0><<<grid, 256, smem>>>(
                A, B, C, M, N, K, lda, ldb, ldc, nH, sAb, sAh, sBb, sBh, sCb,
                sCh, alpha, cdiag, iminus, act, bias, add);
        }
    }
}

extern "C" void kernel_launch(void* const* d_in, const int* in_sizes, int n_in,
                              void* d_out, int out_size) {
    const float* x      = (const float*)d_in[0];
    const float* ln1_g  = (const float*)d_in[1];
    const float* ln1_b  = (const float*)d_in[2];
    const float* w_qkv  = (const float*)d_in[3];
    const float* conv_w = (const float*)d_in[4];
    const float* w_out  = (const float*)d_in[5];
    const float* b_out  = (const float*)d_in[6];
    const float* ln2_g  = (const float*)d_in[7];
    const float* ln2_b  = (const float*)d_in[8];
    const float* w_ff1  = (const float*)d_in[9];
    const float* b_ff1  = (const float*)d_in[10];
    const float* w_ff2  = (const float*)d_in[11];
    const float* b_ff2  = (const float*)d_in[12];
    float* out = (float*)d_out;

    void* p;
    float *xn, *qkvb, *qland, *kland, *a1, *a2, *a3, *z0, *z1, *xz, *u, *v2,
        *w3v, *tb, *aout, *x2, *h1;
    cudaGetSymbolAddress(&p, g_xn);      xn    = (float*)p;
    cudaGetSymbolAddress(&p, g_qkv);     qkvb  = (float*)p;
    cudaGetSymbolAddress(&p, g_qland);   qland = (float*)p;
    cudaGetSymbolAddress(&p, g_kland);   kland = (float*)p;
    cudaGetSymbolAddress(&p, g_attn1);   a1    = (float*)p;
    cudaGetSymbolAddress(&p, g_attn2);   a2    = (float*)p;
    cudaGetSymbolAddress(&p, g_attn3);   a3    = (float*)p;
    cudaGetSymbolAddress(&p, g_z0);      z0    = (float*)p;
    cudaGetSymbolAddress(&p, g_z1);      z1    = (float*)p;
    cudaGetSymbolAddress(&p, g_xz);      xz    = (float*)p;
    cudaGetSymbolAddress(&p, g_u);       u     = (float*)p;
    cudaGetSymbolAddress(&p, g_v2);      v2    = (float*)p;
    cudaGetSymbolAddress(&p, g_w3v);     w3v   = (float*)p;
    cudaGetSymbolAddress(&p, g_t);       tb    = (float*)p;
    cudaGetSymbolAddress(&p, g_attnout); aout  = (float*)p;
    cudaGetSymbolAddress(&p, g_x2);      x2    = (float*)p;
    cudaGetSymbolAddress(&p, g_h1);      h1    = (float*)p;

    const long long sQb = (long long)NSEQ * 1536;
    const long long sLh = (long long)MLAND * DH;
    const long long sLb = 8 * sLh;
    const long long sA1h = (long long)NSEQ * MLAND;
    const long long sA1b = 8 * sA1h;
    const long long sA2h = (long long)MLAND * MLAND;
    const long long sA2b = 8 * sA2h;
    const long long sA3h = (long long)MLAND * NSEQ;
    const long long sA3b = 8 * sA3h;

    // 1. LN1
    layernorm_kernel<<<ROWS, 128>>>(x, ln1_g, ln1_b, xn);
    // 2. QKV projection
    gemm(xn, w_qkv, qkvb, ROWS, 1536, 512, 512, 1536, 1536, 1, 1,
         0, 0, 0, 0, 0, 0, 1.f, 0.f, 0, 0, 0, nullptr, nullptr);
    // 3. Landmark means
    landmark_kernel<<<BHB * MLAND, 64>>>(qkvb, qland, kland);
    // 4. sim1 = scale * q @ k_land^T
    gemm(qkvb, kland, a1, NSEQ, MLAND, DH, 1536, 64, MLAND, BHB, 8,
         sQb, 64, sLb, sLh, sA1b, sA1h, SCALE_Q, 0.f, 1, 0, 0, nullptr, nullptr);
    // 5. sim2 = scale * q_land @ k_land^T
    gemm(qland, kland, a2, MLAND, MLAND, DH, 64, 64, MLAND, BHB, 8,
         sLb, sLh, sLb, sLh, sA2b, sA2h, SCALE_Q, 0.f, 1, 0, 0, nullptr, nullptr);
    // 6. sim3 = scale * q_land @ k^T
    gemm(qland, qkvb + 512, a3, MLAND, NSEQ, DH, 64, 1536, NSEQ, BHB, 8,
         sLb, sLh, sQb, 64, sA3b, sA3h, SCALE_Q, 0.f, 1, 0, 0, nullptr, nullptr);
    // 7. softmaxes
    softmax_kernel<1><<<BHB * NSEQ, 256>>>(a1);
    softmax_kernel<1><<<BHB * MLAND, 256>>>(a2);
    softmax_kernel<16><<<BHB * MLAND, 256>>>(a3);
    // 8. pinv init
    pinv_reset<<<1, 1>>>();
    pinv_absrowmax<<<BHB * MLAND, 256>>>(a2);
    pinv_abscolmax<<<BHB * MLAND, 256>>>(a2);
    pinv_finalize<<<1, 1>>>();
    pinv_initz<<<(BHB * MLAND * MLAND) / 256, 256>>>(a2, z0);
    // 9. 6 Newton-Schulz iterations (I-minus folded into B load)
    float* zA = z0;
    float* zB = z1;
    for (int it = 0; it < 6; it++) {
        gemm(a2, zA, xz, MLAND, MLAND, MLAND, 256, 256, 256, BHB, 8,
             sA2b, sA2h, sA2b, sA2h, sA2b, sA2h, 1.f, 0.f, 0, 0, 0, nullptr, nullptr);
        gemm(xz, xz, u, MLAND, MLAND, MLAND, 256, 256, 256, BHB, 8,
             sA2b, sA2h, sA2b, sA2h, sA2b, sA2h, 1.f, 7.f, 0, 1, 0, nullptr, nullptr);
        gemm(xz, u, v2, MLAND, MLAND, MLAND, 256, 256, 256, BHB, 8,
             sA2b, sA2h, sA2b, sA2h, sA2b, sA2h, 1.f, 15.f, 0, 1, 0, nullptr, nullptr);
        gemm(zA, v2, zB, MLAND, MLAND, MLAND, 256, 256, 256, BHB, 8,
             sA2b, sA2h, sA2b, sA2h, sA2b, sA2h, 0.25f, 13.f, 0, 1, 0, nullptr, nullptr);
        float* tmp = zA; zA = zB; zB = tmp;
    }
    // 10. w3v = attn3 @ v  (M=256, N=64 -> BM=64 instance)
    gemm(a3, qkvb + 1024, w3v, MLAND, DH, NSEQ, NSEQ, 1536, DH, BHB, 8,
         sA3b, sA3h, sQb, 64, sLb, sLh, 1.f, 0.f, 0, 0, 0, nullptr, nullptr);
    // 11. t = attn1 @ attn2_inv
    gemm(a1, zA, tb, NSEQ, MLAND, MLAND, 256, 256, 256, BHB, 8,
         sA1b, sA1h, sA2b, sA2h, sA1b, sA1h, 1.f, 0.f, 0, 0, 0, nullptr, nullptr);
    // 12. out_heads = t @ w3v
    gemm(tb, w3v, aout, NSEQ, DH, MLAND, 256, 64, 512, BHB, 8,
         sA1b, sA1h, sLb, sLh, (long long)NSEQ * 512, 64,
         1.f, 0.f, 0, 0, 0, nullptr, nullptr);
    // 13. depthwise conv residual
    convres_kernel<<<(B_ * NSEQ * NHEAD * DH) / 256, 256>>>(qkvb, conv_w, aout);
    // 14. out projection + bias + residual(x)
    gemm(aout, w_out, x2, ROWS, 512, 512, 512, 512, 512, 1, 1,
         0, 0, 0, 0, 0, 0, 1.f, 0.f, 0, 0, 0, b_out, x);
    // 15. LN2
    layernorm_kernel<<<ROWS, 128>>>(x2, ln2_g, ln2_b, xn);
    // 16. FF1 + bias + exact GELU
    gemm(xn, w_ff1, h1, ROWS, 2048, 512, 512, 2048, 2048, 1, 1,
         0, 0, 0, 0, 0, 0, 1.f, 0.f, 0, 0, 1, b_ff1, nullptr);
    // 17. FF2 + bias + residual(x2) -> out
    gemm(h1, w_ff2, out, ROWS, 512, 2048, 2048, 512, 512, 1, 1,
         0, 0, 0, 0, 0, 0, 1.f, 0.f, 0, 0, 0, b_ff2, x2);
}

// round 10
// speedup vs baseline: 3.1232x; 1.1833x over previous
#include <cuda_runtime.h>
#include <math.h>
#include <stdint.h>

// ---------------------------------------------------------------------------
// Problem constants
// ---------------------------------------------------------------------------
#define B_    4
#define NSEQ  4096
#define DMOD  512
#define NHEAD 8
#define DH    64
#define MLAND 256
#define LTOK  16
#define ROWS  (B_ * NSEQ)   // 16384
#define BHB   (B_ * NHEAD)  // 32
#define SCALE_Q 0.125f

// ---------------------------------------------------------------------------
// Scratch (static device allocations; no cudaMalloc allowed)
// ---------------------------------------------------------------------------
__device__ float g_xn[ROWS * DMOD];
__device__ float g_qkv[ROWS * 3 * DMOD];
__device__ float g_qland[BHB * MLAND * DH];
__device__ float g_kland[BHB * MLAND * DH];
__device__ float g_attn1[BHB * NSEQ * MLAND];
__device__ float g_attn2[BHB * MLAND * MLAND];
__device__ float g_attn3[BHB * MLAND * NSEQ];
__device__ float g_z0[BHB * MLAND * MLAND];
__device__ float g_z1[BHB * MLAND * MLAND];
__device__ float g_xz[BHB * MLAND * MLAND];
__device__ float g_u[BHB * MLAND * MLAND];
__device__ float g_v2[BHB * MLAND * MLAND];
__device__ float g_w3v[BHB * MLAND * DH];
__device__ float g_t[BHB * NSEQ * MLAND];
__device__ float g_attnout[ROWS * DMOD];
__device__ float g_x2[ROWS * DMOD];
__device__ float g_h1[ROWS * 4 * DMOD];
__device__ float g_wq[DMOD * 3 * DMOD];   // tf32-rounded weight copies
__device__ float g_wo[DMOD * DMOD];
__device__ float g_wf1[DMOD * 4 * DMOD];
__device__ float g_wf2[4 * DMOD * DMOD];
__device__ int   g_norm_a;
__device__ int   g_norm_b;
__device__ float g_zscale;

// ---------------------------------------------------------------------------
// Helpers
// ---------------------------------------------------------------------------
__device__ __forceinline__ float warp_sum(float v) {
#pragma unroll
    for (int o = 16; o; o >>= 1) v += __shfl_xor_sync(0xffffffffu, v, o);
    return v;
}
__device__ __forceinline__ float warp_max(float v) {
#pragma unroll
    for (int o = 16; o; o >>= 1) v = fmaxf(v, __shfl_xor_sync(0xffffffffu, v, o));
    return v;
}
__device__ float block_sum(float v) {
    __shared__ float sh[32];
    int lane = threadIdx.x & 31, wid = threadIdx.x >> 5;
    v = warp_sum(v);
    __syncthreads();
    if (lane == 0) sh[wid] = v;
    __syncthreads();
    int nw = blockDim.x >> 5;
    float r = (lane < nw) ? sh[lane] : 0.f;
    return warp_sum(r);
}
__device__ float block_max(float v) {
    __shared__ float sh[32];
    int lane = threadIdx.x & 31, wid = threadIdx.x >> 5;
    v = warp_max(v);
    __syncthreads();
    if (lane == 0) sh[wid] = v;
    __syncthreads();
    int nw = blockDim.x >> 5;
    float r = (lane < nw) ? sh[lane] : -3.0e38f;
    return warp_max(r);
}

__device__ __forceinline__ float gelu_f(float x) {
    return 0.5f * x * (1.f + erff(x * 0.7071067811865476f));
}
__device__ __forceinline__ uint32_t f2tf(float x) {
    uint32_t r;
    asm("cvt.rna.tf32.f32 %0, %1;" : "=r"(r) : "f"(x));
    return r;
}
__device__ __forceinline__ float tf32r(float x) {
    return __uint_as_float(f2tf(x));
}
__device__ __forceinline__ void mma_tf32(float* c, const uint32_t* a,
                                         const uint32_t* b) {
    asm volatile(
        "mma.sync.aligned.m16n8k8.row.col.f32.tf32.tf32.f32 "
        "{%0,%1,%2,%3}, {%4,%5,%6,%7}, {%8,%9}, {%0,%1,%2,%3};\n"
        : "+f"(c[0]), "+f"(c[1]), "+f"(c[2]), "+f"(c[3])
        : "r"(a[0]), "r"(a[1]), "r"(a[2]), "r"(a[3]), "r"(b[0]), "r"(b[1]));
}

#define CP_ASYNC16(dst_u32, src_ptr)                                  \
    asm volatile("cp.async.cg.shared.global [%0], [%1], 16;\n" ::     \
                     "r"(dst_u32), "l"(src_ptr))
#define CP_COMMIT() asm volatile("cp.async.commit_group;\n" ::)
#define CP_WAIT(n)  asm volatile("cp.async.wait_group %0;\n" ::"n"(n))

// ---------------------------------------------------------------------------
// TF32 tensor-core batched GEMM, cp.async 3-stage pipeline.
//   C = rnd?( act( alpha * A @ B' + bias ) + addscale * addsrc )
//   TRANSB=0: B' = B (K x N).  TRANSB=1: B' = B^T (B is N x K).
// Operands must already be tf32-rounded values (producers round).
// BN=64, BK=32. 256 threads. M % BM == 0, N % 64 == 0, K % 32 == 0.
// ---------------------------------------------------------------------------
template <int BM, int WARPS_M, int WARPS_N, int TRANSB>
__global__ __launch_bounds__(256)
void gemm_tc(const float* __restrict__ A, const float* __restrict__ B,
             float* __restrict__ C,
             int M, int N, int K, int lda, int ldb, int ldc, int nH,
             long long sAb, long long sAh, long long sBb, long long sBh,
             long long sCb, long long sCh,
             float alpha, float addscale, int act, int rnd,
             const float* __restrict__ bias, const float* __restrict__ addsrc) {
    constexpr int STAGES = 3;
    constexpr int ASTG = BM * 32;                     // floats per A stage
    constexpr int BSTG = TRANSB ? 64 * 32 : 32 * 68;  // floats per B stage
    constexpr int WM = BM / WARPS_M;                  // 32
    constexpr int WN = 64 / WARPS_N;                  // 32 or 16
    constexpr int MF = WM / 16;                       // 2
    constexpr int NF = WN / 8;                        // 4 or 2
    constexpr int AV = (BM * 8) / 256;                // A 16B-chunks per thread

    extern __shared__ float smbuf[];
    float* As = smbuf;
    float* Bs = smbuf + STAGES * ASTG;

    const int z = blockIdx.z;
    const int zb = z / nH, zh = z - zb * nH;
    A += zb * sAb + zh * sAh;
    B += zb * sBb + zh * sBh;
    const long long coff = zb * sCb + zh * sCh;
    C += coff;

    const int m0 = blockIdx.y * BM;
    const int n0 = blockIdx.x * 64;
    const int tid = threadIdx.x;
    const int lane = tid & 31;
    const int g = lane >> 2, t4 = lane & 3;
    const int wid = tid >> 5;
    const int wm = wid / WARPS_N;
    const int wn = wid % WARPS_N;

    const uint32_t sAbase =
        (uint32_t)__cvta_generic_to_shared(As);
    const uint32_t sBbase =
        (uint32_t)__cvta_generic_to_shared(Bs);

    // per-thread cp.async endpoints (k-advance added per stage)
    const float* agsrc[AV];
    uint32_t asdst[AV];
#pragma unroll
    for (int i = 0; i < AV; i++) {
        int f = tid + 256 * i;
        int r = f >> 3, c4 = f & 7;
        agsrc[i] = A + (long long)(m0 + r) * lda + (c4 << 2);
        asdst[i] = (uint32_t)((r * 32 + ((c4 ^ (r & 7)) << 2)) * 4);
    }
    const float* bgsrc[2];
    uint32_t bsdst[2];
#pragma unroll
    for (int i = 0; i < 2; i++) {
        int f = tid + 256 * i;
        if (TRANSB) {
            int nn = f >> 3, c4 = f & 7;
            bgsrc[i] = B + (long long)(n0 + nn) * ldb + (c4 << 2);
            bsdst[i] = (uint32_t)((nn * 32 + ((c4 ^ (nn & 7)) << 2)) * 4);
        } else {
            int k = f >> 4, c4 = f & 15;
            bgsrc[i] = B + (long long)k * ldb + n0 + (c4 << 2);
            bsdst[i] = (uint32_t)((k * 68 + (c4 << 2)) * 4);
        }
    }

    const int KT = K / 32;

    auto issue = [&](int kt) {
        const int stg = kt % STAGES;
        const uint32_t ao = sAbase + (uint32_t)(stg * ASTG * 4);
        const long long ka = (long long)kt * 32;
#pragma unroll
        for (int i = 0; i < AV; i++) CP_ASYNC16(ao + asdst[i], agsrc[i] + ka);
        const uint32_t bo = sBbase + (uint32_t)(stg * BSTG * 4);
        const long long kb = TRANSB ? (long long)kt * 32
                                    : (long long)kt * 32 * ldb;
#pragma unroll
        for (int i = 0; i < 2; i++) CP_ASYNC16(bo + bsdst[i], bgsrc[i] + kb);
        CP_COMMIT();
    };

    float acc[MF][NF][4];
#pragma unroll
    for (int mi = 0; mi < MF; mi++)
#pragma unroll
        for (int ni = 0; ni < NF; ni++)
#pragma unroll
            for (int q = 0; q < 4; q++) acc[mi][ni][q] = 0.f;

    const int pro = (STAGES - 1 < KT) ? STAGES - 1 : KT;
    for (int s = 0; s < pro; s++) issue(s);

    const int rowA = wm * WM + g;
    const int colB = wn * WN + g;

    for (int kt = 0; kt < KT; kt++) {
        if (kt + 1 < KT) { CP_WAIT(1); } else { CP_WAIT(0); }
        __syncthreads();
        if (kt + STAGES - 1 < KT) issue(kt + STAGES - 1);

        const int stg = kt % STAGES;
        const uint32_t* aU =
            reinterpret_cast<const uint32_t*>(As + stg * ASTG);
        const uint32_t* bU =
            reinterpret_cast<const uint32_t*>(Bs + stg * BSTG);

#pragma unroll
        for (int ks = 0; ks < 4; ks++) {
            const int ca0 = ((2 * ks) ^ g) * 4 + t4;
            const int ca1 = ((2 * ks + 1) ^ g) * 4 + t4;
            uint32_t afr[MF][4];
            uint32_t bfr[NF][2];
#pragma unroll
            for (int mi = 0; mi < MF; mi++) {
                const int r = rowA + mi * 16;
                afr[mi][0] = aU[r * 32 + ca0];
                afr[mi][1] = aU[(r + 8) * 32 + ca0];
                afr[mi][2] = aU[r * 32 + ca1];
                afr[mi][3] = aU[(r + 8) * 32 + ca1];
            }
#pragma unroll
            for (int ni = 0; ni < NF; ni++) {
                if (TRANSB) {
                    const int c = colB + ni * 8;
                    bfr[ni][0] = bU[c * 32 + ca0];
                    bfr[ni][1] = bU[c * 32 + ca1];
                } else {
                    const int kk = ks * 8 + t4;
                    const int c = colB + ni * 8;
                    bfr[ni][0] = bU[kk * 68 + c];
                    bfr[ni][1] = bU[(kk + 4) * 68 + c];
                }
            }
#pragma unroll
            for (int mi = 0; mi < MF; mi++)
#pragma unroll
                for (int ni = 0; ni < NF; ni++)
                    mma_tf32(acc[mi][ni], afr[mi], bfr[ni]);
        }
    }

    // ---- epilogue ----
#pragma unroll
    for (int mi = 0; mi < MF; mi++) {
#pragma unroll
        for (int ni = 0; ni < NF; ni++) {
            const int c = n0 + wn * WN + ni * 8 + t4 * 2;
            float bx = 0.f, by = 0.f;
            if (bias) { bx = bias[c]; by = bias[c + 1]; }
#pragma unroll
            for (int h2 = 0; h2 < 2; h2++) {
                const int m = m0 + wm * WM + mi * 16 + g + h2 * 8;
                float v0 = alpha * acc[mi][ni][h2 * 2 + 0] + bx;
                float v1 = alpha * acc[mi][ni][h2 * 2 + 1] + by;
                if (act) { v0 = gelu_f(v0); v1 = gelu_f(v1); }
                if (addsrc) {
                    float2 av = *reinterpret_cast<const float2*>(
                        addsrc + coff + (long long)m * ldc + c);
                    v0 += addscale * av.x;
                    v1 += addscale * av.y;
                }
                if (rnd) { v0 = tf32r(v0); v1 = tf32r(v1); }
                float2 o; o.x = v0; o.y = v1;
                *reinterpret_cast<float2*>(C + (long long)m * ldc + c) = o;
            }
        }
    }
}

// ---------------------------------------------------------------------------
// LayerNorm (outputs tf32-rounded: feeds GEMM operands)
// ---------------------------------------------------------------------------
__global__ __launch_bounds__(128)
void layernorm_kernel(const float* __restrict__ x, const float* __restrict__ g,
                      const float* __restrict__ b, float* __restrict__ out) {
    long long row = blockIdx.x;
    const float* xr = x + row * DMOD;
    float v[4];
    float s = 0.f;
#pragma unroll
    for (int i = 0; i < 4; i++) { v[i] = xr[i * 128 + threadIdx.x]; s += v[i]; }
    s = block_sum(s);
    float mu = s * (1.f / DMOD);
    float s2 = 0.f;
#pragma unroll
    for (int i = 0; i < 4; i++) { float d = v[i] - mu; s2 += d * d; }
    s2 = block_sum(s2);
    float rstd = rsqrtf(s2 * (1.f / DMOD) + 1e-5f);
#pragma unroll
    for (int i = 0; i < 4; i++) {
        int c = i * 128 + threadIdx.x;
        out[row * DMOD + c] = tf32r((v[i] - mu) * rstd * g[c] + b[c]);
    }
}

// ---------------------------------------------------------------------------
// Landmark means (rounded)
// ---------------------------------------------------------------------------
__global__ __launch_bounds__(64)
void landmark_kernel(const float* __restrict__ qkv, float* __restrict__ qland,
                     float* __restrict__ kland) {
    int idx = blockIdx.x;
    int m = idx & 255;
    int bh = idx >> 8;
    int b = bh >> 3, h = bh & 7;
    int d = threadIdx.x;
    const float* base =
        qkv + ((long long)(b * NSEQ + m * LTOK)) * 1536 + h * 64 + d;
    float sq = 0.f, sk = 0.f;
#pragma unroll
    for (int i = 0; i < LTOK; i++) {
        sq += base[(long long)i * 1536];
        sk += base[(long long)i * 1536 + 512];
    }
    long long o = ((long long)bh * 256 + m) * 64 + d;
    qland[o] = tf32r(sq * (1.f / 16.f));
    kland[o] = tf32r(sk * (1.f / 16.f));
}

// ---------------------------------------------------------------------------
// Row softmax (rounded output: feeds GEMM operands)
// ---------------------------------------------------------------------------
template <int PER>
__global__ __launch_bounds__(256)
void softmax_kernel(float* __restrict__ x) {
    float* xr = x + (long long)blockIdx.x * (PER * 256);
    float v[PER];
    float mx = -3.0e38f;
#pragma unroll
    for (int i = 0; i < PER; i++) {
        v[i] = xr[i * 256 + threadIdx.x];
        mx = fmaxf(mx, v[i]);
    }
    mx = block_max(mx);
    float s = 0.f;
#pragma unroll
    for (int i = 0; i < PER; i++) { v[i] = __expf(v[i] - mx); s += v[i]; }
    s = block_sum(s);
    float inv = 1.f / s;
#pragma unroll
    for (int i = 0; i < PER; i++)
        xr[i * 256 + threadIdx.x] = tf32r(v[i] * inv);
}

// ---------------------------------------------------------------------------
// Pinv helpers
// ---------------------------------------------------------------------------
__global__ void pinv_reset() { g_norm_a = 0; g_norm_b = 0; }

__global__ __launch_bounds__(256)
void pinv_absrowmax(const float* __restrict__ a2) {
    long long r = blockIdx.x;
    float s = block_sum(fabsf(a2[r * 256 + threadIdx.x]));
    if (threadIdx.x == 0) atomicMax(&g_norm_a, __float_as_int(s));
}
__global__ __launch_bounds__(256)
void pinv_abscolmax(const float* __restrict__ a2) {
    int bh = blockIdx.x >> 8, j = blockIdx.x & 255;
    float s = block_sum(fabsf(a2[((long long)bh << 16) + threadIdx.x * 256 + j]));
    if (threadIdx.x == 0) atomicMax(&g_norm_b, __float_as_int(s));
}
__global__ void pinv_finalize() {
    g_zscale = 1.f / (__int_as_float(g_norm_a) * __int_as_float(g_norm_b));
}
__global__ __launch_bounds__(256)
void pinv_initz(const float* __restrict__ a2, float* __restrict__ z) {
    int idx = blockIdx.x * 256 + threadIdx.x;
    int j = idx & 255;
    int i = (idx >> 8) & 255;
    int bh = idx >> 16;
    z[idx] = tf32r(a2[((long long)bh << 16) + (j << 8) + i] * g_zscale);
}

// ---------------------------------------------------------------------------
// Depthwise conv residual (kernel 33, pad 16); rounds (aout feeds outproj A)
// ---------------------------------------------------------------------------
__global__ __launch_bounds__(256)
void convres_kernel(const float* __restrict__ qkv, const float* __restrict__ w,
                    float* __restrict__ out) {
    int idx = blockIdx.x * 256 + threadIdx.x;
    int d = idx & 63;
    int h = (idx >> 6) & 7;
    int i = (idx >> 9) & 4095;
    int b = idx >> 21;
    const float* wr = w + h * 33;
    const float* vbase =
        qkv + (long long)b * NSEQ * 1536 + 1024 + h * 64 + d;
    float acc = 0.f;
#pragma unroll
    for (int t = 0; t < 33; t++) {
        int ii = i + t - 16;
        if (ii >= 0 && ii < NSEQ) acc += wr[t] * vbase[(long long)ii * 1536];
    }
    long long o = ((long long)(b * NSEQ + i) << 9) + (h << 6) + d;
    out[o] = tf32r(out[o] + acc);
}

// ---------------------------------------------------------------------------
// tf32 round-copy (weights)
// ---------------------------------------------------------------------------
__global__ __launch_bounds__(256)
void roundcpy_kernel(const float* __restrict__ a, float* __restrict__ o, int n) {
    int i = blockIdx.x * 256 + threadIdx.x;
    if (i < n) o[i] = tf32r(a[i]);
}

// ---------------------------------------------------------------------------
// Host orchestration
// ---------------------------------------------------------------------------
static void gemm(const float* A, const float* B, float* C, int M, int N, int K,
                 int lda, int ldb, int ldc, int Z, int nH,
                 long long sAb, long long sAh, long long sBb, long long sBh,
                 long long sCb, long long sCh,
                 float alpha, int transB, int act, int rnd,
                 const float* bias, const float* add, float addscale) {
    const bool bm64 =
        ((long long)(M / 128) * (N / 64) * Z) < 148 || (M % 128 != 0);
    if (!bm64) {
        dim3 grid(N / 64, M / 128, Z);
        if (transB) {
            const int smem = 3 * (128 * 32 + 64 * 32) * 4;
            cudaFuncSetAttribute(gemm_tc<128, 4, 2, 1>,
                                 cudaFuncAttributeMaxDynamicSharedMemorySize, smem);
            gemm_tc<128, 4, 2, 1><<<grid, 256, smem>>>(
                A, B, C, M, N, K, lda, ldb, ldc, nH, sAb, sAh, sBb, sBh, sCb,
                sCh, alpha, addscale, act, rnd, bias, add);
        } else {
            const int smem = 3 * (128 * 32 + 32 * 68) * 4;
            cudaFuncSetAttribute(gemm_tc<128, 4, 2, 0>,
                                 cudaFuncAttributeMaxDynamicSharedMemorySize, smem);
            gemm_tc<128, 4, 2, 0><<<grid, 256, smem>>>(
                A, B, C, M, N, K, lda, ldb, ldc, nH, sAb, sAh, sBb, sBh, sCb,
                sCh, alpha, addscale, act, rnd, bias, add);
        }
    } else {
        dim3 grid(N / 64, M / 64, Z);
        if (transB) {
            const int smem = 3 * (64 * 32 + 64 * 32) * 4;
            cudaFuncSetAttribute(gemm_tc<64, 2, 4, 1>,
                                 cudaFuncAttributeMaxDynamicSharedMemorySize, smem);
            gemm_tc<64, 2, 4, 1><<<grid, 256, smem>>>(
                A, B, C, M, N, K, lda, ldb, ldc, nH, sAb, sAh, sBb, sBh, sCb,
                sCh, alpha, addscale, act, rnd, bias, add);
        } else {
            const int smem = 3 * (64 * 32 + 32 * 68) * 4;
            cudaFuncSetAttribute(gemm_tc<64, 2, 4, 0>,
                                 cudaFuncAttributeMaxDynamicSharedMemorySize, smem);
            gemm_tc<64, 2, 4, 0><<<grid, 256, smem>>>(
                A, B, C, M, N, K, lda, ldb, ldc, nH, sAb, sAh, sBb, sBh, sCb,
                sCh, alpha, addscale, act, rnd, bias, add);
        }
    }
}

extern "C" void kernel_launch(void* const* d_in, const int* in_sizes, int n_in,
                              void* d_out, int out_size) {
    const float* x      = (const float*)d_in[0];
    const float* ln1_g  = (const float*)d_in[1];
    const float* ln1_b  = (const float*)d_in[2];
    const float* w_qkv  = (const float*)d_in[3];
    const float* conv_w = (const float*)d_in[4];
    const float* w_out  = (const float*)d_in[5];
    const float* b_out  = (const float*)d_in[6];
    const float* ln2_g  = (const float*)d_in[7];
    const float* ln2_b  = (const float*)d_in[8];
    const float* w_ff1  = (const float*)d_in[9];
    const float* b_ff1  = (const float*)d_in[10];
    const float* w_ff2  = (const float*)d_in[11];
    const float* b_ff2  = (const float*)d_in[12];
    float* out = (float*)d_out;

    void* p;
    float *xn, *qkvb, *qland, *kland, *a1, *a2, *a3, *z0, *z1, *xz, *u, *v2,
        *w3v, *tb, *aout, *x2, *h1, *wq, *wo, *wf1, *wf2;
    cudaGetSymbolAddress(&p, g_xn);      xn    = (float*)p;
    cudaGetSymbolAddress(&p, g_qkv);     qkvb  = (float*)p;
    cudaGetSymbolAddress(&p, g_qland);   qland = (float*)p;
    cudaGetSymbolAddress(&p, g_kland);   kland = (float*)p;
    cudaGetSymbolAddress(&p, g_attn1);   a1    = (float*)p;
    cudaGetSymbolAddress(&p, g_attn2);   a2    = (float*)p;
    cudaGetSymbolAddress(&p, g_attn3);   a3    = (float*)p;
    cudaGetSymbolAddress(&p, g_z0);      z0    = (float*)p;
    cudaGetSymbolAddress(&p, g_z1);      z1    = (float*)p;
    cudaGetSymbolAddress(&p, g_xz);      xz    = (float*)p;
    cudaGetSymbolAddress(&p, g_u);       u     = (float*)p;
    cudaGetSymbolAddress(&p, g_v2);      v2    = (float*)p;
    cudaGetSymbolAddress(&p, g_w3v);     w3v   = (float*)p;
    cudaGetSymbolAddress(&p, g_t);       tb    = (float*)p;
    cudaGetSymbolAddress(&p, g_attnout); aout  = (float*)p;
    cudaGetSymbolAddress(&p, g_x2);      x2    = (float*)p;
    cudaGetSymbolAddress(&p, g_h1);      h1    = (float*)p;
    cudaGetSymbolAddress(&p, g_wq);      wq    = (float*)p;
    cudaGetSymbolAddress(&p, g_wo);      wo    = (float*)p;
    cudaGetSymbolAddress(&p, g_wf1);     wf1   = (float*)p;
    cudaGetSymbolAddress(&p, g_wf2);     wf2   = (float*)p;

    const long long sQb = (long long)NSEQ * 1536;
    const long long sLh = (long long)MLAND * DH;
    const long long sLb = 8 * sLh;
    const long long sA1h = (long long)NSEQ * MLAND;
    const long long sA1b = 8 * sA1h;
    const long long sA2h = (long long)MLAND * MLAND;
    const long long sA2b = 8 * sA2h;
    const long long sA3h = (long long)MLAND * NSEQ;
    const long long sA3b = 8 * sA3h;

    // 0. round weight copies to tf32
    roundcpy_kernel<<<(DMOD * 3 * DMOD + 255) / 256, 256>>>(w_qkv, wq, DMOD * 3 * DMOD);
    roundcpy_kernel<<<(DMOD * DMOD + 255) / 256, 256>>>(w_out, wo, DMOD * DMOD);
    roundcpy_kernel<<<(DMOD * 4 * DMOD + 255) / 256, 256>>>(w_ff1, wf1, DMOD * 4 * DMOD);
    roundcpy_kernel<<<(4 * DMOD * DMOD + 255) / 256, 256>>>(w_ff2, wf2, 4 * DMOD * DMOD);

    // 1. LN1 (rounded)
    layernorm_kernel<<<ROWS, 128>>>(x, ln1_g, ln1_b, xn);
    // 2. QKV projection (rounded out: feeds sims / landmarks / conv)
    gemm(xn, wq, qkvb, ROWS, 1536, 512, 512, 1536, 1536, 1, 1,
         0, 0, 0, 0, 0, 0, 1.f, 0, 0, 1, nullptr, nullptr, 0.f);
    // 3. Landmark means (rounded)
    landmark_kernel<<<BHB * MLAND, 64>>>(qkvb, qland, kland);
    // 4. sim1 = scale * q @ k_land^T
    gemm(qkvb, kland, a1, NSEQ, MLAND, DH, 1536, 64, MLAND, BHB, 8,
         sQb, 64, sLb, sLh, sA1b, sA1h, SCALE_Q, 1, 0, 0, nullptr, nullptr, 0.f);
    // 5. sim2 = scale * q_land @ k_land^T
    gemm(qland, kland, a2, MLAND, MLAND, DH, 64, 64, MLAND, BHB, 8,
         sLb, sLh, sLb, sLh, sA2b, sA2h, SCALE_Q, 1, 0, 0, nullptr, nullptr, 0.f);
    // 6. sim3 = scale * q_land @ k^T
    gemm(qland, qkvb + 512, a3, MLAND, NSEQ, DH, 64, 1536, NSEQ, BHB, 8,
         sLb, sLh, sQb, 64, sA3b, sA3h, SCALE_Q, 1, 0, 0, nullptr, nullptr, 0.f);
    // 7. softmaxes (rounded)
    softmax_kernel<1><<<BHB * NSEQ, 256>>>(a1);
    softmax_kernel<1><<<BHB * MLAND, 256>>>(a2);
    softmax_kernel<16><<<BHB * MLAND, 256>>>(a3);
    // 8. pinv init
    pinv_reset<<<1, 1>>>();
    pinv_absrowmax<<<BHB * MLAND, 256>>>(a2);
    pinv_abscolmax<<<BHB * MLAND, 256>>>(a2);
    pinv_finalize<<<1, 1>>>();
    pinv_initz<<<(BHB * MLAND * MLAND) / 256, 256>>>(a2, z0);
    // 9. 6 Newton-Schulz iterations; (cI - Y) folded into epilogue scaled-add:
    //    X@(cI - Y) = -X@Y + c*X
    float* zA = z0;
    float* zB = z1;
    for (int it = 0; it < 6; it++) {
        // xz = a2 @ zA
        gemm(a2, zA, xz, MLAND, MLAND, MLAND, 256, 256, 256, BHB, 8,
             sA2b, sA2h, sA2b, sA2h, sA2b, sA2h, 1.f, 0, 0, 1, nullptr, nullptr, 0.f);
        // u = xz@(7I - xz) = -xz@xz + 7*xz
        gemm(xz, xz, u, MLAND, MLAND, MLAND, 256, 256, 256, BHB, 8,
             sA2b, sA2h, sA2b, sA2h, sA2b, sA2h, -1.f, 0, 0, 1, nullptr, xz, 7.f);
        // v2 = xz@(15I - u) = -xz@u + 15*xz
        gemm(xz, u, v2, MLAND, MLAND, MLAND, 256, 256, 256, BHB, 8,
             sA2b, sA2h, sA2b, sA2h, sA2b, sA2h, -1.f, 0, 0, 1, nullptr, xz, 15.f);
        // zB = 0.25*zA@(13I - v2) = -0.25*zA@v2 + 3.25*zA
        gemm(zA, v2, zB, MLAND, MLAND, MLAND, 256, 256, 256, BHB, 8,
             sA2b, sA2h, sA2b, sA2h, sA2b, sA2h, -0.25f, 0, 0, 1, nullptr, zA, 3.25f);
        float* tmp = zA; zA = zB; zB = tmp;
    }
    // 10. w3v = attn3 @ v
    gemm(a3, qkvb + 1024, w3v, MLAND, DH, NSEQ, NSEQ, 1536, DH, BHB, 8,
         sA3b, sA3h, sQb, 64, sLb, sLh, 1.f, 0, 0, 1, nullptr, nullptr, 0.f);
    // 11. t = attn1 @ attn2_inv
    gemm(a1, zA, tb, NSEQ, MLAND, MLAND, 256, 256, 256, BHB, 8,
         sA1b, sA1h, sA2b, sA2h, sA1b, sA1h, 1.f, 0, 0, 1, nullptr, nullptr, 0.f);
    // 12. out_heads = t @ w3v  (convres rounds after adding)
    gemm(tb, w3v, aout, NSEQ, DH, MLAND, 256, 64, 512, BHB, 8,
         sA1b, sA1h, sLb, sLh, (long long)NSEQ * 512, 64,
         1.f, 0, 0, 0, nullptr, nullptr, 0.f);
    // 13. depthwise conv residual (+round)
    convres_kernel<<<(B_ * NSEQ * NHEAD * DH) / 256, 256>>>(qkvb, conv_w, aout);
    // 14. out projection + bias + residual(x)  (full fp32 out)
    gemm(aout, wo, x2, ROWS, 512, 512, 512, 512, 512, 1, 1,
         0, 0, 0, 0, 0, 0, 1.f, 0, 0, 0, b_out, x, 1.f);
    // 15. LN2 (rounded)
    layernorm_kernel<<<ROWS, 128>>>(x2, ln2_g, ln2_b, xn);
    // 16. FF1 + bias + exact GELU (rounded: feeds FF2 A)
    gemm(xn, wf1, h1, ROWS, 2048, 512, 512, 2048, 2048, 1, 1,
         0, 0, 0, 0, 0, 0, 1.f, 0, 1, 1, b_ff1, nullptr, 0.f);
    // 17. FF2 + bias + residual(x2) -> out (full fp32)
    gemm(h1, wf2, out, ROWS, 512, 2048, 2048, 512, 512, 1, 1,
         0, 0, 0, 0, 0, 0, 1.f, 0, 0, 0, b_ff2, x2, 1.f);
}